// round 9
// baseline (speedup 1.0000x reference)
#include <cuda_runtime.h>
#include <math.h>

// Problem constants: z_e (16,256,32,32) f32, codebook (8192,256) f32
#define NB    16
#define ND    256
#define NHW   1024
#define NROWS 16384   // NB*NHW
#define NK    8192

// GEMM tiling
#define BM    64
#define BN    128
#define BKc   32
#define KSPLIT 8
#define KS_CODES (NK/KSPLIT)     // 1024 codes per split-block
#define NTILES   (KS_CODES/BN)   // 8
#define CBS   130                // EVEN padded stride: 8B-aligned LDS.64 code pairs

// Output layout: [z_q_st (4194304)] [vq_loss (1)] [indices (16384)] [perplexity (1)]
#define OUT_ZQ   0
#define OUT_LOSS 4194304
#define OUT_IDX  4194305
#define OUT_PERP (4194305 + 16384)

// Scratch (no allocations allowed)
__device__ float  g_Bsq[NK];
__device__ int    g_hist[NK];
__device__ int    g_idx[NROWS];
__device__ float  g_cand_d[NROWS * KSPLIT];
__device__ int    g_cand_i[NROWS * KSPLIT];
__device__ double g_mse_part[4096];

// ---------------------------------------------------------------------------
__global__ void init_kernel() {
    int t = blockIdx.x * blockDim.x + threadIdx.x;
    if (t < NK) g_hist[t] = 0;
}

// ||e_k||^2 per codebook row (B ~1e-6 << ulp(A~256): cannot affect argmin rounding)
__global__ void bsq_kernel(const float* __restrict__ cb) {
    int row  = blockIdx.x * 8 + (threadIdx.x >> 5);
    int lane = threadIdx.x & 31;
    const float* p = cb + (size_t)row * ND;
    float s = 0.f;
#pragma unroll
    for (int j = 0; j < 8; j++) { float v = p[lane + 32 * j]; s = fmaf(v, v, s); }
#pragma unroll
    for (int o = 16; o > 0; o >>= 1) s += __shfl_xor_sync(0xffffffffu, s, o);
    if (lane == 0) g_Bsq[row] = s;
}

// ---------------------------------------------------------------------------
// Fused GEMM + argmin using packed fp32 FMA (fma.rn.f32x2, sm_100+).
// Each f32x2 lane performs IEEE fp32 RN in the SAME accumulation order as the
// scalar version -> bit-identical distances -> bit-identical argmin.
// Thread handles codes k = 2*tx + 32*j2 + q (q = lane in pair), j2 = 0..3.
__global__ void __launch_bounds__(128, 2)
vq_main(const float* __restrict__ ze, const float* __restrict__ cb) {
    extern __shared__ float smem[];
    float* z_s   = smem;                      // [256][64]  d-major
    float* cb_s  = z_s + ND * BM;             // [32][CBS]  d-major rows, k contiguous
    float* A_s   = cb_s + BKc * CBS;          // [64]
    float* red_d = A_s + BM;                  // [64][16]
    int*   red_i = (int*)(red_d + BM * 16);   // [64][16]

    const int tid = threadIdx.x;
    const int tx = tid & 15, ty = tid >> 4;
    const int r0  = blockIdx.x * BM;
    const int ks0 = blockIdx.y * KS_CODES;
    const int b   = r0 / NHW, hw0 = r0 % NHW;
    const float* zbase = ze + (size_t)b * ND * NHW + hw0;

    // Prefetch first cb chunk (tile 0, d in [0,32)) into registers
    float4 creg[8];
    {
#pragma unroll
        for (int m = 0; m < 8; m++) {
            int lin = m * 128 + tid; int kl = lin >> 3; int d4 = lin & 7;
            creg[m] = *(const float4*)(cb + (size_t)(ks0 + kl) * ND + d4 * 4);
        }
    }

    // Load z tile: for each d, 64 consecutive hw -> fully coalesced
    for (int i = tid; i < ND * BM; i += 128) {
        int d = i >> 6, rr = i & 63;
        z_s[i] = zbase[(size_t)d * NHW + rr];   // z_s[d][rr], stride 64
    }
    __syncthreads();

    // A_r = sum z^2 (identical across the split-blocks of the same rows)
    if (tid < BM) {
        float a = 0.f;
#pragma unroll 8
        for (int d = 0; d < ND; d++) { float v = z_s[d * BM + tid]; a = fmaf(v, v, a); }
        A_s[tid] = a;
    }

    unsigned long long acc2[8][4];   // f32x2 pairs: lo = code 2tx+32j, hi = +1
    float mind[8]; int mini[8];
#pragma unroll
    for (int i = 0; i < 8; i++) {
        mind[i] = INFINITY; mini[i] = 0;
#pragma unroll
        for (int j = 0; j < 4; j++) acc2[i][j] = 0ULL;
    }

    const int NIT = NTILES * 8;   // 8 code tiles x 8 d-chunks
    for (int it = 0; it < NIT; ++it) {
        __syncthreads();
        // STS current chunk (CBS=130: 2-way store conflict, negligible vs compute)
#pragma unroll
        for (int m = 0; m < 8; m++) {
            int lin = m * 128 + tid; int kl = lin >> 3; int dd = (lin & 7) * 4;
            cb_s[(dd + 0) * CBS + kl] = creg[m].x;
            cb_s[(dd + 1) * CBS + kl] = creg[m].y;
            cb_s[(dd + 2) * CBS + kl] = creg[m].z;
            cb_s[(dd + 3) * CBS + kl] = creg[m].w;
        }
        __syncthreads();
        // Prefetch next chunk while computing this one
        if (it + 1 < NIT) {
            int nit = it + 1;
            int kbt = ks0 + (nit >> 3) * BN; int d0 = (nit & 7) * BKc;
#pragma unroll
            for (int m = 0; m < 8; m++) {
                int lin = m * 128 + tid; int kl = lin >> 3; int d4 = lin & 7;
                creg[m] = *(const float4*)(cb + (size_t)(kbt + kl) * ND + d0 + d4 * 4);
            }
        }
        // 32 d-steps, 32 packed FFMA2 each (64 fp32 FMA). z index uses this
        // chunk's global d-range, matching cb_s (R7 fix).
        const int zoff = (it & 7) * (BKc * BM);
#pragma unroll 4
        for (int dd = 0; dd < BKc; ++dd) {
            float4 za = *(const float4*)&z_s[zoff + dd * BM + ty * 8];
            float4 zb = *(const float4*)&z_s[zoff + dd * BM + ty * 8 + 4];
            float zr[8] = {za.x, za.y, za.z, za.w, zb.x, zb.y, zb.z, zb.w};
            unsigned long long z2[8];
#pragma unroll
            for (int i = 0; i < 8; i++)
                asm("mov.b64 %0, {%1, %1};" : "=l"(z2[i]) : "f"(zr[i]));
            unsigned long long cf2[4];
#pragma unroll
            for (int j = 0; j < 4; j++)
                cf2[j] = *(const unsigned long long*)&cb_s[dd * CBS + 2 * tx + 32 * j];
#pragma unroll
            for (int i = 0; i < 8; i++)
#pragma unroll
                for (int j = 0; j < 4; j++)
                    asm("fma.rn.f32x2 %0, %1, %2, %0;"
                        : "+l"(acc2[i][j]) : "l"(z2[i]), "l"(cf2[j]));
        }
        // Epilogue once per code tile: fp32 dist exactly like reference, running argmin
        if ((it & 7) == 7) {
            int kb = ks0 + (it >> 3) * BN;
            float Ar[8];
#pragma unroll
            for (int i = 0; i < 8; i++) Ar[i] = A_s[ty * 8 + i];
#pragma unroll
            for (int j = 0; j < 4; j++) {
                int k0 = kb + 2 * tx + 32 * j;          // ascending k across q, j, tiles
                float Bq0 = g_Bsq[k0], Bq1 = g_Bsq[k0 + 1];
#pragma unroll
                for (int i = 0; i < 8; i++) {
                    float a0, a1;
                    asm("mov.b64 {%0, %1}, %2;" : "=f"(a0), "=f"(a1) : "l"(acc2[i][j]));
                    float T0  = __fadd_rn(Ar[i], Bq0);
                    float dv0 = __fmaf_rn(-2.0f, a0, T0);
                    if (dv0 < mind[i]) { mind[i] = dv0; mini[i] = k0; }
                    float T1  = __fadd_rn(Ar[i], Bq1);
                    float dv1 = __fmaf_rn(-2.0f, a1, T1);
                    if (dv1 < mind[i]) { mind[i] = dv1; mini[i] = k0 + 1; }
                    acc2[i][j] = 0ULL;
                }
            }
        }
    }

    // Cross-thread per-row reduction (lexicographic (d, idx) for exact first-min tie-break)
#pragma unroll
    for (int i = 0; i < 8; i++) {
        int row = ty * 8 + i;
        red_d[row * 16 + tx] = mind[i];
        red_i[row * 16 + tx] = mini[i];
    }
    __syncthreads();
    if (tid < BM) {
        float bd = red_d[tid * 16]; int bi = red_i[tid * 16];
#pragma unroll
        for (int t = 1; t < 16; t++) {
            float d2 = red_d[tid * 16 + t]; int i2 = red_i[tid * 16 + t];
            if (d2 < bd || (d2 == bd && i2 < bi)) { bd = d2; bi = i2; }
        }
        int r = r0 + tid;
        g_cand_d[r * KSPLIT + blockIdx.y] = bd;
        g_cand_i[r * KSPLIT + blockIdx.y] = bi;
    }
}

// ---------------------------------------------------------------------------
__global__ void merge_kernel(float* __restrict__ out) {
    int r = blockIdx.x * blockDim.x + threadIdx.x;
    if (r >= NROWS) return;
    float bd = g_cand_d[r * KSPLIT]; int bi = g_cand_i[r * KSPLIT];
#pragma unroll
    for (int s = 1; s < KSPLIT; s++) {
        float d2 = g_cand_d[r * KSPLIT + s];
        if (d2 < bd) { bd = d2; bi = g_cand_i[r * KSPLIT + s]; }  // splits ascending in k
    }
    g_idx[r] = bi;
    atomicAdd(&g_hist[bi], 1);
    out[OUT_IDX + r] = (float)bi;
}

// z_q gather back to (B,D,H,W) + deterministic per-block MSE partials.
// z_q_st emulated exactly: fadd(z_e, fsub(z_q, z_e)).
__global__ void gather_kernel(const float* __restrict__ ze, const float* __restrict__ cb,
                              float* __restrict__ out) {
    __shared__ int   idx_s[32];
    __shared__ float q_s[32][33];
    __shared__ double rsum[8];
    int tid = threadIdx.x;
    int hw0 = blockIdx.x * 32, d0 = blockIdx.y * 32, b = blockIdx.z;
    if (tid < 32) idx_s[tid] = g_idx[b * NHW + hw0 + tid];
    __syncthreads();
    {
        int hh = tid >> 5, dd = tid & 31;
#pragma unroll
        for (int p = 0; p < 4; p++) {
            int h2 = hh + p * 8;
            q_s[h2][dd] = cb[(size_t)idx_s[h2] * ND + d0 + dd];   // coalesced cb row reads
        }
    }
    __syncthreads();
    double acc = 0.0;
    {
        int hh = tid & 31, db = tid >> 5;
#pragma unroll
        for (int p = 0; p < 4; p++) {
            int dd = db + p * 8;
            float q = q_s[hh][dd];
            size_t o = ((size_t)(b * ND + d0 + dd)) * NHW + hw0 + hh;  // coalesced out/ze
            float zv = ze[o];
            float df = __fsub_rn(q, zv);                 // RN(z_q - z_e)
            out[OUT_ZQ + o] = __fadd_rn(zv, df);         // reference z_q_st bit-exact
            acc += (double)df * (double)df;
        }
    }
#pragma unroll
    for (int o = 16; o > 0; o >>= 1) acc += __shfl_xor_sync(0xffffffffu, acc, o);
    if ((tid & 31) == 0) rsum[tid >> 5] = acc;
    __syncthreads();
    if (tid == 0) {
        double s = 0.0;
#pragma unroll
        for (int w = 0; w < 8; w++) s += rsum[w];
        int pid = blockIdx.x + 32 * (blockIdx.y + 8 * blockIdx.z);
        g_mse_part[pid] = s;   // per-block slot: no atomics, deterministic
    }
}

__global__ void finalize_kernel(float* __restrict__ out) {
    __shared__ double sm[256], se[256];
    int tid = threadIdx.x;
    double s = 0.0;
    for (int i = tid; i < 4096; i += 256) s += g_mse_part[i];
    double e = 0.0;
    for (int k = tid; k < NK; k += 256) {
        int c = g_hist[k];
        if (c) {
            float avg = (float)c * (1.0f / 16384.0f);       // exact (pow-2 divide)
            e += (double)(avg * logf(avg + 1e-10f));        // per-term fp32 like reference
        }
    }
    sm[tid] = s; se[tid] = e;
    __syncthreads();
    for (int o = 128; o > 0; o >>= 1) {
        if (tid < o) { sm[tid] += sm[tid + o]; se[tid] += se[tid + o]; }
        __syncthreads();
    }
    if (tid == 0) {
        float m = (float)(sm[0] / (double)((size_t)NROWS * ND));
        out[OUT_LOSS] = __fadd_rn(m, 0.25f * m);    // codebook + BETA*commitment (equal values)
        out[OUT_PERP] = expf(-(float)se[0]);
    }
}

// ---------------------------------------------------------------------------
extern "C" void kernel_launch(void* const* d_in, const int* in_sizes, int n_in,
                              void* d_out, int out_size) {
    const float* ze = (const float*)d_in[0];
    const float* cb = (const float*)d_in[1];
    if (n_in >= 2 && in_sizes[0] == NK * ND) {   // insurance against input-order surprises
        ze = (const float*)d_in[1];
        cb = (const float*)d_in[0];
    }
    float* out = (float*)d_out;

    const int smem_bytes = (ND * BM + BKc * CBS + BM + BM * 16) * 4 + BM * 16 * 4;  // 90624
    cudaFuncSetAttribute(vq_main, cudaFuncAttributeMaxDynamicSharedMemorySize, smem_bytes);

    init_kernel<<<32, 256>>>();
    bsq_kernel<<<NK / 8, 256>>>(cb);
    dim3 g1(NROWS / BM, KSPLIT);
    vq_main<<<g1, 128, smem_bytes>>>(ze, cb);
    merge_kernel<<<NROWS / 256, 256>>>(out);
    gather_kernel<<<dim3(NHW / 32, ND / 32, NB), 256>>>(ze, cb, out);
    finalize_kernel<<<1, 256>>>(out);
}

// round 10
// speedup vs baseline: 1.4267x; 1.4267x over previous
#include <cuda_runtime.h>
#include <math.h>

// Problem constants: z_e (16,256,32,32) f32, codebook (8192,256) f32
#define NB    16
#define ND    256
#define NHW   1024
#define NROWS 16384   // NB*NHW
#define NK    8192

// GEMM tiling: 64 rows x 256 codes per CTA tile, 128 threads, 8x16 micro-tile.
// 0.75 smem-B/FMA -> crossbar (128B/cyc/SM) no longer binds at 2 CTAs/SM.
#define BM    64
#define BN    256
#define BKc   16
#define KSPLIT 8
#define KS_CODES (NK/KSPLIT)     // 1024 codes per split-block
#define NTILES   (KS_CODES/BN)   // 4
#define NCHUNK   (ND/BKc)        // 16 d-chunks per tile
#define CBS   258                // padded stride: conflict-free STS & broadcast LDS

// Output layout: [z_q_st (4194304)] [vq_loss (1)] [indices (16384)] [perplexity (1)]
#define OUT_ZQ   0
#define OUT_LOSS 4194304
#define OUT_IDX  4194305
#define OUT_PERP (4194305 + 16384)

// Scratch (no allocations allowed)
__device__ float  g_Bsq[NK];
__device__ int    g_hist[NK];
__device__ int    g_idx[NROWS];
__device__ float  g_cand_d[NROWS * KSPLIT];
__device__ int    g_cand_i[NROWS * KSPLIT];
__device__ double g_mse_part[4096];

// ---------------------------------------------------------------------------
__global__ void init_kernel() {
    int t = blockIdx.x * blockDim.x + threadIdx.x;
    if (t < NK) g_hist[t] = 0;
}

// ||e_k||^2 per codebook row (B ~1e-6 << ulp(A~256): cannot affect argmin rounding)
__global__ void bsq_kernel(const float* __restrict__ cb) {
    int row  = blockIdx.x * 8 + (threadIdx.x >> 5);
    int lane = threadIdx.x & 31;
    const float* p = cb + (size_t)row * ND;
    float s = 0.f;
#pragma unroll
    for (int j = 0; j < 8; j++) { float v = p[lane + 32 * j]; s = fmaf(v, v, s); }
#pragma unroll
    for (int o = 16; o > 0; o >>= 1) s += __shfl_xor_sync(0xffffffffu, s, o);
    if (lane == 0) g_Bsq[row] = s;
}

// ---------------------------------------------------------------------------
// Fused fp32 GEMM + argmin. Scalar FFMA (R9's f32x2 regressed: same HW FMA
// units, no throughput gain). Per-(row,code) accumulation is d=0..255
// sequential fmaf -> bit-identical distances to the reference pipeline.
// Thread (tx 0..15, ty 0..7): rows ty*8..+7, codes tx + 16*j (j=0..15).
__global__ void __launch_bounds__(128, 2)
vq_main(const float* __restrict__ ze, const float* __restrict__ cb) {
    extern __shared__ float smem[];
    float* z_s   = smem;                      // [256][64]  d-major
    float* cb_s  = z_s + ND * BM;             // [16][CBS]  d rows, 256 codes each
    float* A_s   = cb_s + BKc * CBS;          // [64]
    float* red_d = A_s + BM;                  // [64][16]
    int*   red_i = (int*)(red_d + BM * 16);   // [64][16]

    const int tid = threadIdx.x;
    const int tx = tid & 15, ty = tid >> 4;
    const int r0  = blockIdx.x * BM;
    const int ks0 = blockIdx.y * KS_CODES;
    const int b   = r0 / NHW, hw0 = r0 % NHW;
    const float* zbase = ze + (size_t)b * ND * NHW + hw0;

    // Prefetch first cb chunk (tile 0, d in [0,16)) into registers.
    // lin -> (kl = lin>>2 in [0,256), d4 = lin&3): float4 of 4 d-values.
    float4 creg[8];
    {
#pragma unroll
        for (int m = 0; m < 8; m++) {
            int lin = m * 128 + tid; int kl = lin >> 2; int d4 = lin & 3;
            creg[m] = *(const float4*)(cb + (size_t)(ks0 + kl) * ND + d4 * 4);
        }
    }

    // Load z tile: for each d, 64 consecutive hw -> fully coalesced
    for (int i = tid; i < ND * BM; i += 128) {
        int d = i >> 6, rr = i & 63;
        z_s[i] = zbase[(size_t)d * NHW + rr];   // z_s[d][rr], stride 64
    }
    __syncthreads();

    // A_r = sum z^2 (d-ascending fmaf; identical across split-blocks)
    if (tid < BM) {
        float a = 0.f;
#pragma unroll 8
        for (int d = 0; d < ND; d++) { float v = z_s[d * BM + tid]; a = fmaf(v, v, a); }
        A_s[tid] = a;
    }

    float acc[8][16]; float mind[8]; int mini[8];
#pragma unroll
    for (int i = 0; i < 8; i++) {
        mind[i] = INFINITY; mini[i] = 0;
#pragma unroll
        for (int j = 0; j < 16; j++) acc[i][j] = 0.f;
    }

    const int NIT = NTILES * NCHUNK;   // 4 code tiles x 16 d-chunks = 64
    for (int it = 0; it < NIT; ++it) {
        __syncthreads();
        // STS current chunk. Bank = kl0 + (l>>2) + 8(l&3) + 2q mod 32:
        // all 32 lanes distinct -> conflict-free.
#pragma unroll
        for (int m = 0; m < 8; m++) {
            int lin = m * 128 + tid; int kl = lin >> 2; int dd = (lin & 3) * 4;
            cb_s[(dd + 0) * CBS + kl] = creg[m].x;
            cb_s[(dd + 1) * CBS + kl] = creg[m].y;
            cb_s[(dd + 2) * CBS + kl] = creg[m].z;
            cb_s[(dd + 3) * CBS + kl] = creg[m].w;
        }
        __syncthreads();
        // Prefetch next chunk while computing this one
        if (it + 1 < NIT) {
            int nit = it + 1;
            int kbt = ks0 + (nit >> 4) * BN; int d0 = (nit & 15) * BKc;
#pragma unroll
            for (int m = 0; m < 8; m++) {
                int lin = m * 128 + tid; int kl = lin >> 2; int d4 = lin & 3;
                creg[m] = *(const float4*)(cb + (size_t)(kbt + kl) * ND + d0 + d4 * 4);
            }
        }
        // 16 d-steps x 128 FFMA. z index uses this chunk's global d-range.
        const int zoff = (it & 15) * (BKc * BM);
#pragma unroll 4
        for (int dd = 0; dd < BKc; ++dd) {
            float4 za = *(const float4*)&z_s[zoff + dd * BM + ty * 8];
            float4 zb = *(const float4*)&z_s[zoff + dd * BM + ty * 8 + 4];
            float zr[8] = {za.x, za.y, za.z, za.w, zb.x, zb.y, zb.z, zb.w};
            float cf[16];
#pragma unroll
            for (int j = 0; j < 16; j++) cf[j] = cb_s[dd * CBS + tx + 16 * j];
#pragma unroll
            for (int i = 0; i < 8; i++)
#pragma unroll
                for (int j = 0; j < 16; j++) acc[i][j] = fmaf(zr[i], cf[j], acc[i][j]);
        }
        // Epilogue once per code tile: fp32 dist exactly like reference, running argmin
        if ((it & 15) == 15) {
            int kb = ks0 + (it >> 4) * BN;
            float Ar[8];
#pragma unroll
            for (int i = 0; i < 8; i++) Ar[i] = A_s[ty * 8 + i];
#pragma unroll
            for (int j = 0; j < 16; j++) {
                int kk = kb + tx + 16 * j;        // ascending k across j and tiles
                float Bq = g_Bsq[kk];
#pragma unroll
                for (int i = 0; i < 8; i++) {
                    float T  = __fadd_rn(Ar[i], Bq);
                    float dv = __fmaf_rn(-2.0f, acc[i][j], T);
                    if (dv < mind[i]) { mind[i] = dv; mini[i] = kk; }  // strict < keeps first
                    acc[i][j] = 0.f;
                }
            }
        }
    }

    // Cross-thread per-row reduction (lexicographic (d, idx): exact first-min tie-break,
    // invariant to the code->thread assignment)
#pragma unroll
    for (int i = 0; i < 8; i++) {
        int row = ty * 8 + i;
        red_d[row * 16 + tx] = mind[i];
        red_i[row * 16 + tx] = mini[i];
    }
    __syncthreads();
    if (tid < BM) {
        float bd = red_d[tid * 16]; int bi = red_i[tid * 16];
#pragma unroll
        for (int t = 1; t < 16; t++) {
            float d2 = red_d[tid * 16 + t]; int i2 = red_i[tid * 16 + t];
            if (d2 < bd || (d2 == bd && i2 < bi)) { bd = d2; bi = i2; }
        }
        int r = r0 + tid;
        g_cand_d[r * KSPLIT + blockIdx.y] = bd;
        g_cand_i[r * KSPLIT + blockIdx.y] = bi;
    }
}

// ---------------------------------------------------------------------------
__global__ void merge_kernel(float* __restrict__ out) {
    int r = blockIdx.x * blockDim.x + threadIdx.x;
    if (r >= NROWS) return;
    float bd = g_cand_d[r * KSPLIT]; int bi = g_cand_i[r * KSPLIT];
#pragma unroll
    for (int s = 1; s < KSPLIT; s++) {
        float d2 = g_cand_d[r * KSPLIT + s];
        if (d2 < bd) { bd = d2; bi = g_cand_i[r * KSPLIT + s]; }  // splits ascending in k
    }
    g_idx[r] = bi;
    atomicAdd(&g_hist[bi], 1);
    out[OUT_IDX + r] = (float)bi;
}

// z_q gather back to (B,D,H,W) + deterministic per-block MSE partials.
// z_q_st emulated exactly: fadd(z_e, fsub(z_q, z_e)).
__global__ void gather_kernel(const float* __restrict__ ze, const float* __restrict__ cb,
                              float* __restrict__ out) {
    __shared__ int   idx_s[32];
    __shared__ float q_s[32][33];
    __shared__ double rsum[8];
    int tid = threadIdx.x;
    int hw0 = blockIdx.x * 32, d0 = blockIdx.y * 32, b = blockIdx.z;
    if (tid < 32) idx_s[tid] = g_idx[b * NHW + hw0 + tid];
    __syncthreads();
    {
        int hh = tid >> 5, dd = tid & 31;
#pragma unroll
        for (int p = 0; p < 4; p++) {
            int h2 = hh + p * 8;
            q_s[h2][dd] = cb[(size_t)idx_s[h2] * ND + d0 + dd];   // coalesced cb row reads
        }
    }
    __syncthreads();
    double acc = 0.0;
    {
        int hh = tid & 31, db = tid >> 5;
#pragma unroll
        for (int p = 0; p < 4; p++) {
            int dd = db + p * 8;
            float q = q_s[hh][dd];
            size_t o = ((size_t)(b * ND + d0 + dd)) * NHW + hw0 + hh;  // coalesced out/ze
            float zv = ze[o];
            float df = __fsub_rn(q, zv);                 // RN(z_q - z_e)
            out[OUT_ZQ + o] = __fadd_rn(zv, df);         // reference z_q_st bit-exact
            acc += (double)df * (double)df;
        }
    }
#pragma unroll
    for (int o = 16; o > 0; o >>= 1) acc += __shfl_xor_sync(0xffffffffu, acc, o);
    if ((tid & 31) == 0) rsum[tid >> 5] = acc;
    __syncthreads();
    if (tid == 0) {
        double s = 0.0;
#pragma unroll
        for (int w = 0; w < 8; w++) s += rsum[w];
        int pid = blockIdx.x + 32 * (blockIdx.y + 8 * blockIdx.z);
        g_mse_part[pid] = s;   // per-block slot: no atomics, deterministic
    }
}

__global__ void finalize_kernel(float* __restrict__ out) {
    __shared__ double sm[256], se[256];
    int tid = threadIdx.x;
    double s = 0.0;
    for (int i = tid; i < 4096; i += 256) s += g_mse_part[i];
    double e = 0.0;
    for (int k = tid; k < NK; k += 256) {
        int c = g_hist[k];
        if (c) {
            float avg = (float)c * (1.0f / 16384.0f);       // exact (pow-2 divide)
            e += (double)(avg * logf(avg + 1e-10f));        // per-term fp32 like reference
        }
    }
    sm[tid] = s; se[tid] = e;
    __syncthreads();
    for (int o = 128; o > 0; o >>= 1) {
        if (tid < o) { sm[tid] += sm[tid + o]; se[tid] += se[tid + o]; }
        __syncthreads();
    }
    if (tid == 0) {
        float m = (float)(sm[0] / (double)((size_t)NROWS * ND));
        out[OUT_LOSS] = __fadd_rn(m, 0.25f * m);    // codebook + BETA*commitment (equal values)
        out[OUT_PERP] = expf(-(float)se[0]);
    }
}

// ---------------------------------------------------------------------------
extern "C" void kernel_launch(void* const* d_in, const int* in_sizes, int n_in,
                              void* d_out, int out_size) {
    const float* ze = (const float*)d_in[0];
    const float* cb = (const float*)d_in[1];
    if (n_in >= 2 && in_sizes[0] == NK * ND) {   // insurance against input-order surprises
        ze = (const float*)d_in[1];
        cb = (const float*)d_in[0];
    }
    float* out = (float*)d_out;

    const int smem_bytes = (ND * BM + BKc * CBS + BM + BM * 16) * 4 + BM * 16 * 4;  // 90496
    cudaFuncSetAttribute(vq_main, cudaFuncAttributeMaxDynamicSharedMemorySize, smem_bytes);

    init_kernel<<<32, 256>>>();
    bsq_kernel<<<NK / 8, 256>>>(cb);
    dim3 g1(NROWS / BM, KSPLIT);
    vq_main<<<g1, 128, smem_bytes>>>(ze, cb);
    merge_kernel<<<NROWS / 256, 256>>>(out);
    gather_kernel<<<dim3(NHW / 32, ND / 32, NB), 256>>>(ze, cb, out);
    finalize_kernel<<<1, 256>>>(out);
}